// round 15
// baseline (speedup 1.0000x reference)
#include <cuda_runtime.h>

#define NUM_LINK 9
#define DOF 7
#define THREADS 256

__device__ __forceinline__ void stcs_f4(float* p, float4 v) {
    asm volatile("st.global.cs.v4.f32 [%0], {%1,%2,%3,%4};"
                 :: "l"(p), "f"(v.x), "f"(v.y), "f"(v.z), "f"(v.w) : "memory");
}

// Batched 7-DOF forward kinematics (B=500k), 4 threads per robot — one
// 4x4-matrix ROW per thread. Row independence: for T' = T @ M, row r of T'
// depends only on row r of T, so the chain runs entirely in 4 registers/lane.
// Joints at links 1..7, axes z,y,z,y,z,y,z (links 0 and 8 fixed); the joint
// multiply is exploited as a 2-column rotation, not a full 4x4 matmul.
// Output stores evict-first (.cs): the 288MB write stream is the DRAM-bound
// component; inputs stay L2-resident across graph replays. Measured at the
// chip's effective DRAM-write ceiling (~5.3 TB/s).
__global__ __launch_bounds__(THREADS)
void fk_kernel(const float* __restrict__ Tbase,
               const float* __restrict__ Toff,
               const float* __restrict__ Q,
               float* __restrict__ out,
               int B)
{
    __shared__ float4 sToff[NUM_LINK * 4];
    if (threadIdx.x < NUM_LINK * 4)
        sToff[threadIdx.x] = reinterpret_cast<const float4*>(Toff)[threadIdx.x];
    __syncthreads();

    int g   = blockIdx.x * blockDim.x + threadIdx.x;
    int b   = g >> 2;           // robot index
    int sub = g & 3;            // row index 0..3
    bool valid = (b < B);
    int bb = valid ? b : (B - 1);   // clamp so shfl participation is uniform

    // Coalesced Tbase row load (warp covers contiguous 512B).
    float4 r = reinterpret_cast<const float4*>(Tbase)[(size_t)bb * 4 + sub];

    // sincos split across the 4 lanes of this robot: lane t -> joints t, t+4.
    const float* qb = Q + (size_t)bb * DOF;
    float s_lo, c_lo, s_hi, c_hi;
    __sincosf(qb[sub], &s_lo, &c_lo);
    __sincosf(qb[sub < 3 ? sub + 4 : 3], &s_hi, &c_hi);  // lane 3 hi unused

    float sj[DOF], cj[DOF];
    #pragma unroll
    for (int j = 0; j < 4; j++) {
        sj[j] = __shfl_sync(0xFFFFFFFFu, s_lo, j, 4);
        cj[j] = __shfl_sync(0xFFFFFFFFu, c_lo, j, 4);
    }
    #pragma unroll
    for (int j = 4; j < DOF; j++) {
        sj[j] = __shfl_sync(0xFFFFFFFFu, s_hi, j - 4, 4);
        cj[j] = __shfl_sync(0xFFFFFFFFu, c_hi, j - 4, 4);
    }

    float* outb = out + (size_t)b * (NUM_LINK * 16) + sub * 4;

    #pragma unroll
    for (int i = 0; i < NUM_LINK; i++) {
        // r = r @ Toff[i]  (row-vector times 4x4; rows broadcast from smem)
        float4 o0 = sToff[i * 4 + 0];
        float4 o1 = sToff[i * 4 + 1];
        float4 o2 = sToff[i * 4 + 2];
        float4 o3 = sToff[i * 4 + 3];
        float4 n;
        n.x = fmaf(r.x, o0.x, fmaf(r.y, o1.x, fmaf(r.z, o2.x, r.w * o3.x)));
        n.y = fmaf(r.x, o0.y, fmaf(r.y, o1.y, fmaf(r.z, o2.y, r.w * o3.y)));
        n.z = fmaf(r.x, o0.z, fmaf(r.y, o1.z, fmaf(r.z, o2.z, r.w * o3.z)));
        n.w = fmaf(r.x, o0.w, fmaf(r.y, o1.w, fmaf(r.z, o2.w, r.w * o3.w)));
        r = n;

        // Revolute joint at links 1..7 (axes z,y,z,y,z,y,z): mixes two columns.
        if (i >= 1 && i <= 7) {
            float s = sj[i - 1], c = cj[i - 1];
            if (i & 1) {        // z: x' = c*x + s*y ; y' = c*y - s*x
                float x = r.x, y = r.y;
                r.x = fmaf(c, x,  s * y);
                r.y = fmaf(c, y, -s * x);
            } else {            // y: x' = c*x - s*z ; z' = c*z + s*x
                float x = r.x, z = r.z;
                r.x = fmaf(c, x, -s * z);
                r.z = fmaf(c, z,  s * x);
            }
        }

        // Store row sub of link i: lanes 4k..4k+3 = one contiguous 64B chunk.
        if (valid)
            stcs_f4(outb + i * 16, r);
    }
}

extern "C" void kernel_launch(void* const* d_in, const int* in_sizes, int n_in,
                              void* d_out, int out_size)
{
    int B = out_size / (NUM_LINK * 16);

    const float* Tbase = nullptr;
    const float* Toff  = nullptr;
    const float* Q     = nullptr;
    for (int i = 0; i < n_in; i++) {
        if (in_sizes[i] == NUM_LINK * 16)      Toff  = (const float*)d_in[i];
        else if (in_sizes[i] == B * 16)        Tbase = (const float*)d_in[i];
        else if (in_sizes[i] == B * DOF)       Q     = (const float*)d_in[i];
    }
    if (!Tbase) Tbase = (const float*)d_in[0];
    if (!Toff)  Toff  = (const float*)d_in[1];
    if (!Q)     Q     = (const float*)d_in[2];

    float* out = (float*)d_out;

    long long total = (long long)B * 4;
    const int blocks = (int)((total + THREADS - 1) / THREADS);
    fk_kernel<<<blocks, THREADS>>>(Tbase, Toff, Q, out, B);
}